// round 13
// baseline (speedup 1.0000x reference)
#include <cuda_runtime.h>
#include <cuda_bf16.h>
#include <math.h>
#include <stdint.h>

#define N_SEQS   2048
#define SEQ_LEN  512
#define N_AA     20
#define M_MI     100
#define N_PAIRS  4950                    // 100*99/2 upper triangle
#define OUT_PSSM 0
#define OUT_CONS (SEQ_LEN * N_AA)        // 10240
#define OUT_MI   (OUT_CONS + SEQ_LEN)    // 10752
#define OUT_TOTAL (OUT_MI + SEQ_LEN * SEQ_LEN)  // 272896

#define CNT_CTAS 256                     // count/pack/zero CTAs (blockIdx 0..255)
#define MI_CTAS  619                     // mi CTAs (blockIdx 256..874)
#define MEGA_CTAS (CNT_CTAS + MI_CTAS)   // 875 <= 148*6 -> single co-resident wave

// Scratch (no dynamic allocation allowed)
__device__ unsigned char g_colpack[128 * N_SEQS];    // column-major int8 msa[:, :128] (100 used)
__device__ int           g_part[16][SEQ_LEN][21];    // count partials (plain stores)
__device__ int           g_pack_done  = 0;           // count CTAs done packing (self-resetting)
__device__ int           g_count_done = 0;           // count CTAs done with g_part (self-resetting)
__device__ int           g_mi_done    = 0;           // mi CTAs past the spin (self-resetting)

// ---------------------------------------------------------------------------
// ONE kernel does everything. Heterogeneous single-wave grid (all 875 CTAs
// co-resident: 6 CTAs/SM x 148 SMs = 888 >= 875; enforced via launch_bounds).
//
//   CTAs 0..255 : (a) pack their 32col x 128row msa slice -> g_colpack,
//                 (b) release mi via g_pack_done (fence + atomic),
//                 (c) per-position AA counts -> g_part,
//                 (d) complement-zero of mi's write set in the MI region,
//                 (e) LAST count CTA (elected via g_count_done) computes
//                     pssm + conservation itself (hidden under mi).
//   CTAs 256..874: spin until g_pack_done == 256, then the proven
//                 ATOMS-floor mi code (untouched). Last mi CTA resets flags.
//
// mi writes exactly the off-diagonal of [0:100)^2; count CTAs zero exactly
// the complement -> disjoint, no ordering needed between them.
// ---------------------------------------------------------------------------
__global__ __launch_bounds__(256, 6) void mega_kernel(const int* __restrict__ msa,
                                                      float* __restrict__ out,
                                                      const float* __restrict__ pc) {
    __shared__ __align__(16) unsigned char smem_raw[28672];
    int b = blockIdx.x;
    int tid = threadIdx.x, lane = tid & 31, w = tid >> 5;
    float* mi_out = out + OUT_MI;

    if (b < CNT_CTAS) {
        // ================= COUNT / PACK / ZERO / PSSM branch =================
        int (*cnt)[32][21] = (int(*)[32][21])smem_raw;   // 8*32*21*4 = 21504 B
        int* slast = (int*)(smem_raw + 21504);           // last-CTA flag
        for (int v = tid; v < 8 * 32 * 21; v += 256) ((int*)cnt)[v] = 0;

        // (d) complement-zero of mi's write set (63136 tasks over 65536 threads)
        int t = b * 256 + tid;
        if (t < 52736) {                                   // rows 100..511, all cols
            int r = 100 + (t >> 7);
            ((float4*)mi_out)[r * 128 + (t & 127)] = make_float4(0.f, 0.f, 0.f, 0.f);
        } else if (t < 63036) {                            // rows 0..99, cols 100..511
            int u = t - 52736;
            int r = u / 103, c4 = 25 + (u - r * 103);
            ((float4*)mi_out)[r * 128 + c4] = make_float4(0.f, 0.f, 0.f, 0.f);
        } else if (t < 63136) {                            // diagonal d<100
            int dd = t - 63036;
            mi_out[dd * SEQ_LEN + dd] = 0.f;
        }

        // (a) load 16 rows of one column; pack + count
        int col   = (b & 15) * 32 + lane;
        int rbase = (b >> 4) * 128 + w * 16;
        int vals[16];
#pragma unroll
        for (int s = 0; s < 16; s++)
            vals[s] = msa[(rbase + s) * SEQ_LEN + col];    // coalesced 128B / warp

        if (col < M_MI) {
            uint32_t pk[4];
#pragma unroll
            for (int g = 0; g < 4; g++)
                pk[g] = (uint32_t)vals[4 * g] | ((uint32_t)vals[4 * g + 1] << 8) |
                        ((uint32_t)vals[4 * g + 2] << 16) | ((uint32_t)vals[4 * g + 3] << 24);
            *(uint4*)&g_colpack[col * N_SEQS + rbase] = make_uint4(pk[0], pk[1], pk[2], pk[3]);
        }

        // (b) release mi: all pack stores fenced, then one arrival per CTA
        __threadfence();
        __syncthreads();
        if (tid == 0) atomicAdd(&g_pack_done, 1);

        // (c) counts into per-warp replica hists (private -> plain RMW)
        int* my = cnt[w][lane];
#pragma unroll
        for (int s = 0; s < 16; s++) my[vals[s]] += 1;
        __syncthreads();

        for (int v = tid; v < 32 * 21; v += 256) {
            int l = v / 21, c = v % 21;
            int s = 0;
#pragma unroll
            for (int ww = 0; ww < 8; ww++) s += cnt[ww][l][c];
            g_part[b >> 4][(b & 15) * 32 + l][c] = s;      // plain store
        }

        // (e) elect the last count CTA to run pssm
        __threadfence();
        __syncthreads();
        if (tid == 0) {
            int old = atomicAdd(&g_count_done, 1);
            *slast = (old == CNT_CTAS - 1);
        }
        __syncthreads();
        if (!*slast) return;

        __threadfence();                                   // acquire g_part
        float pcount = 0.01f * pc[0];
        float inv_den = 1.0f / ((float)N_SEQS + pcount * 20.0f);
        for (int p = w; p < SEQ_LEN; p += 8) {             // warp per position
            int ct = 0;
            if (lane < 20) {
#pragma unroll
                for (int k = 0; k < 16; k++) ct += __ldcg(&g_part[k][p][lane]);
            }
            int tt = ct;
#pragma unroll
            for (int off = 16; off; off >>= 1) tt += __shfl_xor_sync(0xffffffffu, tt, off);
            int total = tt;

            float tinv = 1.0f / fmaxf((float)total, 1.0f);
            float ent = 0.0f;
            if (lane < 20) {
                float freq = ((float)ct + pcount) * inv_den;
                out[OUT_PSSM + p * 20 + lane] = logf(freq * 20.0f + 1e-10f);
                float f = (float)ct * tinv;
                ent = -f * log2f(f + 1e-10f);
            }
#pragma unroll
            for (int off = 16; off; off >>= 1) ent += __shfl_xor_sync(0xffffffffu, ent, off);
            if (lane == 0)
                out[OUT_CONS + p] = (total > 0) ? (1.0f - ent * (1.0f / 4.321928094887362f)) : 0.0f;
        }
        if (tid == 0) { g_count_done = 0; __threadfence(); }
        return;
    }

    // ======================= MI branch (proven code) =======================
    int*   hist = (int*)smem_raw;                          // 8*400*4 = 12800
    float* lut  = (float*)(smem_raw + 12800);              // 2049*4  = 8196
    float* slra = (float*)(smem_raw + 12800 + 8196);       // 640
    float* slcb = (float*)(smem_raw + 12800 + 8196 + 640); // 640

    int wid = w;
    for (int v = tid; v < 2049; v += 256) lut[v] = log2f((float)v);
    for (int v = lane; v < 400; v += 32) hist[wid * 400 + v] = 0;

    // Wait for all pack slices (all 875 CTAs are co-resident -> no deadlock)
    if (tid == 0) {
        volatile int* pd = &g_pack_done;
        while (*pd < CNT_CTAS) __nanosleep(64);
        __threadfence();
    }
    __syncthreads();
    if (tid == 0) {
        int old = atomicAdd(&g_mi_done, 1);                // after spin -> reset is safe
        if (old == MI_CTAS - 1) { g_mi_done = 0; g_pack_done = 0; __threadfence(); }
    }

    int pid = (b - CNT_CTAS) * 8 + wid;
    if (pid >= N_PAIRS) return;

    // Decode upper-triangle pair index -> (i, j), i < j; T(i) = i*(199-i)/2
    float d = sqrtf(39601.0f - 8.0f * (float)pid);
    int i = (int)((199.0f - d) * 0.5f);
    if (i < 0) i = 0;
    if (i > 98) i = 98;
    while ((((i + 1) * (199 - (i + 1))) >> 1) <= pid) ++i;
    while (((i * (199 - i)) >> 1) > pid) --i;
    int j = pid - ((i * (199 - i)) >> 1) + i + 1;

    int* h = hist + wid * 400;

    const uint4* ca = (const uint4*)(g_colpack + i * N_SEQS);
    const uint4* cb = (const uint4*)(g_colpack + j * N_SEQS);
#pragma unroll
    for (int it = 0; it < 4; it++) {                // 4 x LDG.128 per operand
        uint4 va = ca[lane + 32 * it];
        uint4 vb = cb[lane + 32 * it];
        const uint32_t wa_[4] = {va.x, va.y, va.z, va.w};
        const uint32_t wb_[4] = {vb.x, vb.y, vb.z, vb.w};
#pragma unroll
        for (int q = 0; q < 4; q++) {
            uint32_t wa = wa_[q], wb = wb_[q];
#pragma unroll
            for (int s = 0; s < 4; s++) {
                int a  = (wa >> (8 * s)) & 255;
                int bb = (wb >> (8 * s)) & 255;
                if (a < 20 && bb < 20)
                    atomicAdd(&h[a * 20 + bb], 1);
            }
        }
    }
    __syncwarp();

    // Integer marginals over the 20x20 block
    int rs = 0, cs = 0;
    if (lane < 20) {
#pragma unroll
        for (int bq = 0; bq < 20; bq++) { rs += h[lane * 20 + bq]; cs += h[bq * 20 + lane]; }
        slra[wid * 20 + lane] = lut[rs];
        slcb[wid * 20 + lane] = lut[cs];
    }
    int tv = (lane < 20) ? rs : 0;
#pragma unroll
    for (int off = 16; off; off >>= 1) tv += __shfl_xor_sync(0xffffffffu, tv, off);
    int tot = tv;
    __syncwarp();

    int tots = (tot > 0) ? tot : 1;
    float lt = lut[tots];
    float acc = 0.0f;
    for (int c = lane; c < 400; c += 32) {
        int H = h[c];
        if (H > 0) {
            int a = (c * 3277) >> 16;   // c / 20 for c < 400
            int bq = c - a * 20;
            acc += (float)H * (lut[H] - slra[wid * 20 + a] - slcb[wid * 20 + bq] + lt);
        }
    }
#pragma unroll
    for (int off = 16; off; off >>= 1) acc += __shfl_xor_sync(0xffffffffu, acc, off);

    if (lane == 0) {
        float mi = (tot > 0) ? acc / (float)tots : 0.0f;
        mi_out[i * SEQ_LEN + j] = mi;
        mi_out[j * SEQ_LEN + i] = mi;
    }
}

// ---------------------------------------------------------------------------
// Launch: ONE kernel, ONE graph node. All ordering is intra-kernel.
// ---------------------------------------------------------------------------
extern "C" void kernel_launch(void* const* d_in, const int* in_sizes, int n_in,
                              void* d_out, int out_size) {
    const int*   msa = (const int*)d_in[0];
    const float* pc  = (const float*)d_in[1];
    float*       out = (float*)d_out;

    mega_kernel<<<MEGA_CTAS, 256>>>(msa, out, pc);
}

// round 14
// speedup vs baseline: 2.7910x; 2.7910x over previous
#include <cuda_runtime.h>
#include <cuda_bf16.h>
#include <math.h>
#include <stdint.h>

#define N_SEQS   2048
#define SEQ_LEN  512
#define N_AA     20
#define M_MI     100
#define N_PAIRS  4950                    // 100*99/2 upper triangle
#define OUT_PSSM 0
#define OUT_CONS (SEQ_LEN * N_AA)        // 10240
#define OUT_MI   (OUT_CONS + SEQ_LEN)    // 10752
#define OUT_TOTAL (OUT_MI + SEQ_LEN * SEQ_LEN)  // 272896

#define CNT_CTAS 256                     // count/zero CTAs (blockIdx 0..255)
#define MI_CTAS  619                     // mi CTAs (blockIdx 256..874)
#define MEGA_CTAS (CNT_CTAS + MI_CTAS)   // 875

// Scratch (no dynamic allocation allowed)
__device__ unsigned char g_colpack[128 * N_SEQS];    // column-major int8 msa[:, :128] (100 used)
__device__ int           g_part[16][SEQ_LEN][21];    // count partials (plain stores, no zeroing)

// ---------------------------------------------------------------------------
// Pack v2: columns 0..99 -> int8 column-major, MLP-maximized.
// grid (4, 32) x 256 = 32768 threads; each thread issues 8 INDEPENDENT
// scalar LDGs (one 128B line per warp per row) -> the entire 1MB read stream
// is in flight at once (1024 warps x 8 lines). Two uint32 stores via uint2.
// ---------------------------------------------------------------------------
__global__ __launch_bounds__(256) void pack_kernel(const int* __restrict__ msa) {
    int tid = threadIdx.x, lane = tid & 31, w = tid >> 5;
    int col   = blockIdx.x * 32 + lane;          // 0..127 (stores only col<100)
    int rbase = blockIdx.y * 64 + w * 8;

    const int* base = msa + rbase * SEQ_LEN + col;
    int v0 = base[0 * SEQ_LEN], v1 = base[1 * SEQ_LEN];
    int v2 = base[2 * SEQ_LEN], v3 = base[3 * SEQ_LEN];
    int v4 = base[4 * SEQ_LEN], v5 = base[5 * SEQ_LEN];
    int v6 = base[6 * SEQ_LEN], v7 = base[7 * SEQ_LEN];

    uint32_t p0 = (uint32_t)v0 | ((uint32_t)v1 << 8) | ((uint32_t)v2 << 16) | ((uint32_t)v3 << 24);
    uint32_t p1 = (uint32_t)v4 | ((uint32_t)v5 << 8) | ((uint32_t)v6 << 16) | ((uint32_t)v7 << 24);
    if (col < M_MI)
        *(uint2*)&g_colpack[col * N_SEQS + rbase] = make_uint2(p0, p1);
}

// ---------------------------------------------------------------------------
// MEGA kernel (R12, measured-good): heterogeneous grid, NO intra-kernel sync.
//   CTAs 0..255   : per-position AA counts + complement-zero of mi's writes.
//   CTAs 256..874 : mi, one warp per (i<j) pair — proven ATOMS-floor code.
// Write sets in the MI region are disjoint by construction.
// ---------------------------------------------------------------------------
__global__ __launch_bounds__(256) void mega_kernel(const int* __restrict__ msa,
                                                   float* __restrict__ mi_out) {
    __shared__ __align__(16) unsigned char smem_raw[28672];
    int b = blockIdx.x;
    int tid = threadIdx.x, lane = tid & 31, w = tid >> 5;

    if (b < CNT_CTAS) {
        // ----- COUNT + COMPLEMENT-ZERO branch -----
        int (*cnt)[32][21] = (int(*)[32][21])smem_raw;   // 8*32*21*4 = 21504B
        for (int v = tid; v < 8 * 32 * 21; v += 256) ((int*)cnt)[v] = 0;

        // Zero the complement of mi's write set:
        //   rows 100..511 (all cols): 52736 float4
        //   rows 0..99, cols 100..511: 10300 float4 (col 100 = f4 #25)
        //   diagonal (d,d), d<100: 100 scalars
        int t = b * 256 + tid;
        if (t < 52736) {
            int r = 100 + (t >> 7);
            ((float4*)mi_out)[r * 128 + (t & 127)] = make_float4(0.f, 0.f, 0.f, 0.f);
        } else if (t < 63036) {
            int u = t - 52736;
            int r = u / 103, c4 = 25 + (u - r * 103);
            ((float4*)mi_out)[r * 128 + c4] = make_float4(0.f, 0.f, 0.f, 0.f);
        } else if (t < 63136) {
            int dd = t - 63036;
            mi_out[dd * SEQ_LEN + dd] = 0.f;
        }
        __syncthreads();

        int col   = (b & 15) * 32 + lane;
        int rbase = (b >> 4) * 128 + w * 16;
        int* my = cnt[w][lane];
#pragma unroll
        for (int s = 0; s < 16; s++) {
            int c = msa[(rbase + s) * SEQ_LEN + col];   // coalesced 128B per warp
            my[c] += 1;                                  // private replica: plain RMW
        }
        __syncthreads();

        for (int v = tid; v < 32 * 21; v += 256) {
            int l = v / 21, c = v % 21;
            int s = 0;
#pragma unroll
            for (int ww = 0; ww < 8; ww++) s += cnt[ww][l][c];
            g_part[b >> 4][(b & 15) * 32 + l][c] = s;   // plain store
        }
        return;
    }

    // ----- MI branch (proven ATOMS-floor code; smem via overlay pointers) -----
    int*   hist = (int*)smem_raw;                          // 8*400*4 = 12800
    float* lut  = (float*)(smem_raw + 12800);              // 2049*4  = 8196
    float* slra = (float*)(smem_raw + 12800 + 8196);       // 640
    float* slcb = (float*)(smem_raw + 12800 + 8196 + 640); // 640

    int wid = w;
    for (int v = tid; v < 2049; v += 256) lut[v] = log2f((float)v);
    __syncthreads();

    int pid = (b - CNT_CTAS) * 8 + wid;
    if (pid >= N_PAIRS) return;

    // Decode upper-triangle pair index -> (i, j), i < j; T(i) = i*(199-i)/2
    float d = sqrtf(39601.0f - 8.0f * (float)pid);
    int i = (int)((199.0f - d) * 0.5f);
    if (i < 0) i = 0;
    if (i > 98) i = 98;
    while ((((i + 1) * (199 - (i + 1))) >> 1) <= pid) ++i;
    while (((i * (199 - i)) >> 1) > pid) --i;
    int j = pid - ((i * (199 - i)) >> 1) + i + 1;

    int* h = hist + wid * 400;
    for (int v = lane; v < 400; v += 32) h[v] = 0;
    __syncwarp();

    const uint4* ca = (const uint4*)(g_colpack + i * N_SEQS);
    const uint4* cb = (const uint4*)(g_colpack + j * N_SEQS);
#pragma unroll
    for (int it = 0; it < 4; it++) {                // 4 x LDG.128 per operand
        uint4 va = ca[lane + 32 * it];
        uint4 vb = cb[lane + 32 * it];
        const uint32_t wa_[4] = {va.x, va.y, va.z, va.w};
        const uint32_t wb_[4] = {vb.x, vb.y, vb.z, vb.w};
#pragma unroll
        for (int q = 0; q < 4; q++) {
            uint32_t wa = wa_[q], wb = wb_[q];
#pragma unroll
            for (int s = 0; s < 4; s++) {
                int a  = (wa >> (8 * s)) & 255;
                int bb = (wb >> (8 * s)) & 255;
                if (a < 20 && bb < 20)
                    atomicAdd(&h[a * 20 + bb], 1);
            }
        }
    }
    __syncwarp();

    // Integer marginals over the 20x20 block
    int rs = 0, cs = 0;
    if (lane < 20) {
#pragma unroll
        for (int bq = 0; bq < 20; bq++) { rs += h[lane * 20 + bq]; cs += h[bq * 20 + lane]; }
        slra[wid * 20 + lane] = lut[rs];
        slcb[wid * 20 + lane] = lut[cs];
    }
    int tv = (lane < 20) ? rs : 0;
#pragma unroll
    for (int off = 16; off; off >>= 1) tv += __shfl_xor_sync(0xffffffffu, tv, off);
    int tot = tv;
    __syncwarp();

    int tots = (tot > 0) ? tot : 1;
    float lt = lut[tots];
    float acc = 0.0f;
    for (int c = lane; c < 400; c += 32) {
        int H = h[c];
        if (H > 0) {
            int a = (c * 3277) >> 16;   // c / 20 for c < 400
            int bq = c - a * 20;
            acc += (float)H * (lut[H] - slra[wid * 20 + a] - slcb[wid * 20 + bq] + lt);
        }
    }
#pragma unroll
    for (int off = 16; off; off >>= 1) acc += __shfl_xor_sync(0xffffffffu, acc, off);

    if (lane == 0) {
        float mi = (tot > 0) ? acc / (float)tots : 0.0f;
        mi_out[i * SEQ_LEN + j] = mi;
        mi_out[j * SEQ_LEN + i] = mi;
    }
}

// ---------------------------------------------------------------------------
// PSSM + conservation: one warp per position (lane = amino acid); sums the
// 16 count partials. 64 CTAs x 256.
// ---------------------------------------------------------------------------
__global__ __launch_bounds__(256) void pssm_kernel(float* __restrict__ out, const float* __restrict__ pc) {
    int gtid = blockIdx.x * blockDim.x + threadIdx.x;
    int p = gtid >> 5, lane = gtid & 31;
    if (p >= SEQ_LEN) return;

    int ct = 0;
    if (lane < 20) {
#pragma unroll
        for (int k = 0; k < 16; k++) ct += g_part[k][p][lane];
    }

    int t = ct;
#pragma unroll
    for (int off = 16; off; off >>= 1) t += __shfl_xor_sync(0xffffffffu, t, off);
    int total = t;

    float pcount = 0.01f * pc[0];
    float inv_den = 1.0f / ((float)N_SEQS + pcount * 20.0f);
    float tinv = 1.0f / fmaxf((float)total, 1.0f);

    float ent = 0.0f;
    if (lane < 20) {
        float freq = ((float)ct + pcount) * inv_den;
        out[OUT_PSSM + p * 20 + lane] = logf(freq * 20.0f + 1e-10f);
        float f = (float)ct * tinv;
        ent = -f * log2f(f + 1e-10f);
    }
#pragma unroll
    for (int off = 16; off; off >>= 1) ent += __shfl_xor_sync(0xffffffffu, ent, off);
    if (lane == 0)
        out[OUT_CONS + p] = (total > 0) ? (1.0f - ent * (1.0f / 4.321928094887362f)) : 0.0f;
}

// ---------------------------------------------------------------------------
// Launch: SINGLE stream, 3 nodes. Overlap of count under mi happens INSIDE
// mega_kernel (heterogeneous CTAs), ordering via kernel boundaries only.
// ---------------------------------------------------------------------------
extern "C" void kernel_launch(void* const* d_in, const int* in_sizes, int n_in,
                              void* d_out, int out_size) {
    const int*   msa = (const int*)d_in[0];
    const float* pc  = (const float*)d_in[1];
    float*       out = (float*)d_out;

    pack_kernel<<<dim3(4, 32), 256>>>(msa);               // mi's only dependency
    mega_kernel<<<MEGA_CTAS, 256>>>(msa, out + OUT_MI);   // mi + count + zero
    pssm_kernel<<<64, 256>>>(out, pc);                    // pssm + conservation
}

// round 15
// speedup vs baseline: 3.1193x; 1.1176x over previous
#include <cuda_runtime.h>
#include <cuda_bf16.h>
#include <math.h>
#include <stdint.h>

#define N_SEQS   2048
#define SEQ_LEN  512
#define N_AA     20
#define M_MI     100
#define N_PAIRS  4950                    // 100*99/2 upper triangle
#define OUT_PSSM 0
#define OUT_CONS (SEQ_LEN * N_AA)        // 10240
#define OUT_MI   (OUT_CONS + SEQ_LEN)    // 10752
#define OUT_TOTAL (OUT_MI + SEQ_LEN * SEQ_LEN)  // 272896

#define MI_CTAS   619                    // mi CTAs (blockIdx 0..618)
#define AUX_CTAS  64                     // zero + pssm CTAs (blockIdx 619..682)
#define MEGA_CTAS (MI_CTAS + AUX_CTAS)   // 683

// Scratch (no dynamic allocation allowed)
__device__ unsigned char g_colpack[128 * N_SEQS];    // column-major int8 msa[:, :128] (100 used)
__device__ int           g_part[16][SEQ_LEN][21];    // count partials (plain stores, no zeroing)

// ---------------------------------------------------------------------------
// PREP (node 1): pack + per-position counts in one msa pass (R9 measured-good
// shape, MI-zeroing removed). grid (16,16) x 256: CTA covers 32 cols x 128
// rows; thread handles 16 rows of one column (lane = column -> coalesced
// 128B per warp per row). Per-warp replica histograms -> plain smem RMW.
// ---------------------------------------------------------------------------
__global__ __launch_bounds__(256) void prep_kernel(const int* __restrict__ msa) {
    __shared__ int cnt[8][32][21];     // [warp][lane(col)][symbol]
    int tid = threadIdx.x, lane = tid & 31, w = tid >> 5;
    for (int v = tid; v < 8 * 32 * 21; v += 256) ((int*)cnt)[v] = 0;
    __syncthreads();

    int col   = blockIdx.x * 32 + lane;
    int rbase = blockIdx.y * 128 + w * 16;

    int vals[16];
#pragma unroll
    for (int s = 0; s < 16; s++)
        vals[s] = msa[(rbase + s) * SEQ_LEN + col];    // coalesced 128B per warp

    int* my = cnt[w][lane];
#pragma unroll
    for (int s = 0; s < 16; s++) my[vals[s]] += 1;     // private replica: plain RMW

    if (col < M_MI) {                                   // pack 16 rows -> uint4
        uint32_t pk[4];
#pragma unroll
        for (int g = 0; g < 4; g++)
            pk[g] = (uint32_t)vals[4 * g] | ((uint32_t)vals[4 * g + 1] << 8) |
                    ((uint32_t)vals[4 * g + 2] << 16) | ((uint32_t)vals[4 * g + 3] << 24);
        *(uint4*)&g_colpack[col * N_SEQS + rbase] = make_uint4(pk[0], pk[1], pk[2], pk[3]);
    }
    __syncthreads();

    for (int v = tid; v < 32 * 21; v += 256) {
        int l = v / 21, c = v % 21;
        int s = 0;
#pragma unroll
        for (int ww = 0; ww < 8; ww++) s += cnt[ww][l][c];
        g_part[blockIdx.y][blockIdx.x * 32 + l][c] = s;   // plain store
    }
}

// ---------------------------------------------------------------------------
// MEGA (node 2): heterogeneous grid, ordering vs prep via kernel boundary.
//   CTAs 0..618   : mi, one warp per (i<j) pair — proven ATOMS-floor code.
//   CTAs 619..682 : (a) zero the COMPLEMENT of mi's write set in the MI
//                   region (disjoint addresses -> no ordering needed), then
//                   (b) pssm + conservation, one warp per position
//                   (8 positions per CTA). All hidden under mi.
// ---------------------------------------------------------------------------
__global__ __launch_bounds__(256) void mega_kernel(float* __restrict__ out,
                                                   const float* __restrict__ pc) {
    __shared__ int   hist[8][400];
    __shared__ float lut[2049];       // log2(0..2048)
    __shared__ float slra[8][20];
    __shared__ float slcb[8][20];

    int b = blockIdx.x;
    int tid = threadIdx.x, lane = tid & 31, w = tid >> 5;
    float* mi_out = out + OUT_MI;

    if (b >= MI_CTAS) {
        // ================== ZERO-COMPLEMENT + PSSM branch ==================
        int bb = b - MI_CTAS;

        // (a) zero the complement of mi's write set (63136 tasks / 16384 thr)
        for (int t = bb * 256 + tid; t < 63136; t += AUX_CTAS * 256) {
            if (t < 52736) {                               // rows 100..511, all cols
                int r = 100 + (t >> 7);
                ((float4*)mi_out)[r * 128 + (t & 127)] = make_float4(0.f, 0.f, 0.f, 0.f);
            } else if (t < 63036) {                        // rows 0..99, cols 100..511
                int u = t - 52736;
                int r = u / 103, c4 = 25 + (u - r * 103);
                ((float4*)mi_out)[r * 128 + c4] = make_float4(0.f, 0.f, 0.f, 0.f);
            } else {                                       // diagonal d<100
                int dd = t - 63036;
                mi_out[dd * SEQ_LEN + dd] = 0.f;
            }
        }

        // (b) pssm + conservation: warp w -> position bb*8 + w
        int p = bb * 8 + w;                                // 64*8 = 512 positions
        int ct = 0;
        if (lane < 20) {
#pragma unroll
            for (int k = 0; k < 16; k++) ct += g_part[k][p][lane];
        }
        int t = ct;
#pragma unroll
        for (int off = 16; off; off >>= 1) t += __shfl_xor_sync(0xffffffffu, t, off);
        int total = t;

        float pcount = 0.01f * pc[0];
        float inv_den = 1.0f / ((float)N_SEQS + pcount * 20.0f);
        float tinv = 1.0f / fmaxf((float)total, 1.0f);

        float ent = 0.0f;
        if (lane < 20) {
            float freq = ((float)ct + pcount) * inv_den;
            out[OUT_PSSM + p * 20 + lane] = logf(freq * 20.0f + 1e-10f);
            float f = (float)ct * tinv;
            ent = -f * log2f(f + 1e-10f);
        }
#pragma unroll
        for (int off = 16; off; off >>= 1) ent += __shfl_xor_sync(0xffffffffu, ent, off);
        if (lane == 0)
            out[OUT_CONS + p] = (total > 0) ? (1.0f - ent * (1.0f / 4.321928094887362f)) : 0.0f;
        return;
    }

    // ===================== MI branch (proven code) =====================
    int wid = w;
    for (int v = tid; v < 2049; v += 256) lut[v] = log2f((float)v);
    __syncthreads();

    int pid = b * 8 + wid;
    if (pid >= N_PAIRS) return;

    // Decode upper-triangle pair index -> (i, j), i < j; T(i) = i*(199-i)/2
    float d = sqrtf(39601.0f - 8.0f * (float)pid);
    int i = (int)((199.0f - d) * 0.5f);
    if (i < 0) i = 0;
    if (i > 98) i = 98;
    while ((((i + 1) * (199 - (i + 1))) >> 1) <= pid) ++i;
    while (((i * (199 - i)) >> 1) > pid) --i;
    int j = pid - ((i * (199 - i)) >> 1) + i + 1;

    int* h = hist[wid];
    for (int v = lane; v < 400; v += 32) h[v] = 0;
    __syncwarp();

    const uint4* ca = (const uint4*)(g_colpack + i * N_SEQS);
    const uint4* cb = (const uint4*)(g_colpack + j * N_SEQS);
#pragma unroll
    for (int it = 0; it < 4; it++) {                // 4 x LDG.128 per operand
        uint4 va = ca[lane + 32 * it];
        uint4 vb = cb[lane + 32 * it];
        const uint32_t wa_[4] = {va.x, va.y, va.z, va.w};
        const uint32_t wb_[4] = {vb.x, vb.y, vb.z, vb.w};
#pragma unroll
        for (int q = 0; q < 4; q++) {
            uint32_t wa = wa_[q], wb = wb_[q];
#pragma unroll
            for (int s = 0; s < 4; s++) {
                int a  = (wa >> (8 * s)) & 255;
                int bb = (wb >> (8 * s)) & 255;
                if (a < 20 && bb < 20)
                    atomicAdd(&h[a * 20 + bb], 1);
            }
        }
    }
    __syncwarp();

    // Integer marginals over the 20x20 block
    int rs = 0, cs = 0;
    if (lane < 20) {
#pragma unroll
        for (int bq = 0; bq < 20; bq++) { rs += h[lane * 20 + bq]; cs += h[bq * 20 + lane]; }
        slra[wid][lane] = lut[rs];
        slcb[wid][lane] = lut[cs];
    }
    int tv = (lane < 20) ? rs : 0;
#pragma unroll
    for (int off = 16; off; off >>= 1) tv += __shfl_xor_sync(0xffffffffu, tv, off);
    int tot = tv;
    __syncwarp();

    int tots = (tot > 0) ? tot : 1;
    float lt = lut[tots];
    float acc = 0.0f;
    for (int c = lane; c < 400; c += 32) {
        int H = h[c];
        if (H > 0) {
            int a = (c * 3277) >> 16;   // c / 20 for c < 400
            int bq = c - a * 20;
            acc += (float)H * (lut[H] - slra[wid][a] - slcb[wid][bq] + lt);
        }
    }
#pragma unroll
    for (int off = 16; off; off >>= 1) acc += __shfl_xor_sync(0xffffffffu, acc, off);

    if (lane == 0) {
        float mi = (tot > 0) ? acc / (float)tots : 0.0f;
        mi_out[i * SEQ_LEN + j] = mi;
        mi_out[j * SEQ_LEN + i] = mi;
    }
}

// ---------------------------------------------------------------------------
// Launch: SINGLE stream, TWO nodes. prep -> mega (pssm + zero hidden in mega).
// ---------------------------------------------------------------------------
extern "C" void kernel_launch(void* const* d_in, const int* in_sizes, int n_in,
                              void* d_out, int out_size) {
    const int*   msa = (const int*)d_in[0];
    const float* pc  = (const float*)d_in[1];
    float*       out = (float*)d_out;

    prep_kernel<<<dim3(16, 16), 256>>>(msa);        // pack + count partials
    mega_kernel<<<MEGA_CTAS, 256>>>(out, pc);       // mi + (zero + pssm hidden)
}

// round 16
// speedup vs baseline: 3.2222x; 1.0330x over previous
#include <cuda_runtime.h>
#include <cuda_bf16.h>
#include <math.h>
#include <stdint.h>

#define N_SEQS   2048
#define SEQ_LEN  512
#define N_AA     20
#define M_MI     100
#define N_PAIRS  4950                    // 100*99/2 upper triangle
#define OUT_PSSM 0
#define OUT_CONS (SEQ_LEN * N_AA)        // 10240
#define OUT_MI   (OUT_CONS + SEQ_LEN)    // 10752
#define OUT_TOTAL (OUT_MI + SEQ_LEN * SEQ_LEN)  // 272896

#define MI_CTAS   619                    // mi CTAs (blockIdx 0..618)
#define AUX_CTAS  64                     // zero + pssm CTAs (blockIdx 619..682)
#define MEGA_CTAS (MI_CTAS + AUX_CTAS)   // 683

// Scratch (no dynamic allocation allowed)
__device__ unsigned char g_colpack[128 * N_SEQS];    // column-major int8 msa[:, :128] (100 used)
__device__ int           g_part[16][SEQ_LEN][21];    // count partials (plain stores, no zeroing)
__device__ float         g_lut[2049];                // log2(0..2048), written once by prep

// ---------------------------------------------------------------------------
// PREP (node 1): pack + per-position counts in one msa pass. CTA (0,0) also
// writes the global log2 LUT (8 log2f per thread — hidden among 256 CTAs).
// grid (16,16) x 256: CTA covers 32 cols x 128 rows; thread handles 16 rows
// of one column (lane = column -> coalesced 128B per warp per row).
// ---------------------------------------------------------------------------
__global__ __launch_bounds__(256) void prep_kernel(const int* __restrict__ msa) {
    __shared__ int cnt[8][32][21];     // [warp][lane(col)][symbol]
    int tid = threadIdx.x, lane = tid & 31, w = tid >> 5;
    for (int v = tid; v < 8 * 32 * 21; v += 256) ((int*)cnt)[v] = 0;

    if (blockIdx.x == 0 && blockIdx.y == 0) {       // one CTA fills the LUT
        for (int v = tid; v < 2049; v += 256) g_lut[v] = log2f((float)v);
    }
    __syncthreads();

    int col   = blockIdx.x * 32 + lane;
    int rbase = blockIdx.y * 128 + w * 16;

    int vals[16];
#pragma unroll
    for (int s = 0; s < 16; s++)
        vals[s] = msa[(rbase + s) * SEQ_LEN + col];    // coalesced 128B per warp

    int* my = cnt[w][lane];
#pragma unroll
    for (int s = 0; s < 16; s++) my[vals[s]] += 1;     // private replica: plain RMW

    if (col < M_MI) {                                   // pack 16 rows -> uint4
        uint32_t pk[4];
#pragma unroll
        for (int g = 0; g < 4; g++)
            pk[g] = (uint32_t)vals[4 * g] | ((uint32_t)vals[4 * g + 1] << 8) |
                    ((uint32_t)vals[4 * g + 2] << 16) | ((uint32_t)vals[4 * g + 3] << 24);
        *(uint4*)&g_colpack[col * N_SEQS + rbase] = make_uint4(pk[0], pk[1], pk[2], pk[3]);
    }
    __syncthreads();

    for (int v = tid; v < 32 * 21; v += 256) {
        int l = v / 21, c = v % 21;
        int s = 0;
#pragma unroll
        for (int ww = 0; ww < 8; ww++) s += cnt[ww][l][c];
        g_part[blockIdx.y][blockIdx.x * 32 + l][c] = s;   // plain store
    }
}

// ---------------------------------------------------------------------------
// MEGA (node 2): heterogeneous grid, ordering vs prep via kernel boundary.
//   CTAs 0..618   : mi, one warp per (i<j) pair — ATOMS-floor event loop
//                   (proven). Epilogue now reads the L2-resident g_lut via
//                   __ldg: NO per-CTA lut build, NO MUFU, NO __syncthreads.
//   CTAs 619..682 : zero the COMPLEMENT of mi's write set, then pssm +
//                   conservation (one warp per position). Hidden under mi.
// ---------------------------------------------------------------------------
__global__ __launch_bounds__(256) void mega_kernel(float* __restrict__ out,
                                                   const float* __restrict__ pc) {
    __shared__ int   hist[8][400];
    __shared__ float slra[8][20];
    __shared__ float slcb[8][20];

    int b = blockIdx.x;
    int tid = threadIdx.x, lane = tid & 31, w = tid >> 5;
    float* mi_out = out + OUT_MI;

    if (b >= MI_CTAS) {
        // ================== ZERO-COMPLEMENT + PSSM branch ==================
        int bb = b - MI_CTAS;

        // Zero the complement of mi's write set (63136 tasks / 16384 threads)
        for (int t = bb * 256 + tid; t < 63136; t += AUX_CTAS * 256) {
            if (t < 52736) {                               // rows 100..511, all cols
                int r = 100 + (t >> 7);
                ((float4*)mi_out)[r * 128 + (t & 127)] = make_float4(0.f, 0.f, 0.f, 0.f);
            } else if (t < 63036) {                        // rows 0..99, cols 100..511
                int u = t - 52736;
                int r = u / 103, c4 = 25 + (u - r * 103);
                ((float4*)mi_out)[r * 128 + c4] = make_float4(0.f, 0.f, 0.f, 0.f);
            } else {                                       // diagonal d<100
                int dd = t - 63036;
                mi_out[dd * SEQ_LEN + dd] = 0.f;
            }
        }

        // pssm + conservation: warp w -> position bb*8 + w  (64*8 = 512)
        int p = bb * 8 + w;
        int ct = 0;
        if (lane < 20) {
#pragma unroll
            for (int k = 0; k < 16; k++) ct += g_part[k][p][lane];
        }
        int t = ct;
#pragma unroll
        for (int off = 16; off; off >>= 1) t += __shfl_xor_sync(0xffffffffu, t, off);
        int total = t;

        float pcount = 0.01f * pc[0];
        float inv_den = 1.0f / ((float)N_SEQS + pcount * 20.0f);
        float tinv = 1.0f / fmaxf((float)total, 1.0f);

        float ent = 0.0f;
        if (lane < 20) {
            float freq = ((float)ct + pcount) * inv_den;
            out[OUT_PSSM + p * 20 + lane] = logf(freq * 20.0f + 1e-10f);
            float f = (float)ct * tinv;
            ent = -f * log2f(f + 1e-10f);
        }
#pragma unroll
        for (int off = 16; off; off >>= 1) ent += __shfl_xor_sync(0xffffffffu, ent, off);
        if (lane == 0)
            out[OUT_CONS + p] = (total > 0) ? (1.0f - ent * (1.0f / 4.321928094887362f)) : 0.0f;
        return;
    }

    // ===================== MI branch (ATOMS-floor loop) =====================
    int wid = w;
    int pid = b * 8 + wid;
    if (pid >= N_PAIRS) return;

    // Decode upper-triangle pair index -> (i, j), i < j; T(i) = i*(199-i)/2
    float d = sqrtf(39601.0f - 8.0f * (float)pid);
    int i = (int)((199.0f - d) * 0.5f);
    if (i < 0) i = 0;
    if (i > 98) i = 98;
    while ((((i + 1) * (199 - (i + 1))) >> 1) <= pid) ++i;
    while (((i * (199 - i)) >> 1) > pid) --i;
    int j = pid - ((i * (199 - i)) >> 1) + i + 1;

    int* h = hist[wid];
    for (int v = lane; v < 100; v += 32)              // 400 ints = 100 int4
        ((int4*)h)[v] = make_int4(0, 0, 0, 0);
    __syncwarp();

    const uint4* ca = (const uint4*)(g_colpack + i * N_SEQS);
    const uint4* cb = (const uint4*)(g_colpack + j * N_SEQS);
#pragma unroll
    for (int it = 0; it < 4; it++) {                // 4 x LDG.128 per operand
        uint4 va = ca[lane + 32 * it];
        uint4 vb = cb[lane + 32 * it];
        const uint32_t wa_[4] = {va.x, va.y, va.z, va.w};
        const uint32_t wb_[4] = {vb.x, vb.y, vb.z, vb.w};
#pragma unroll
        for (int q = 0; q < 4; q++) {
            uint32_t wa = wa_[q], wb = wb_[q];
#pragma unroll
            for (int s = 0; s < 4; s++) {
                int a  = __byte_perm(wa, 0, 0x4440 | s);  // byte s of wa
                int bb = __byte_perm(wb, 0, 0x4440 | s);  // byte s of wb
                if (a < 20 && bb < 20)
                    atomicAdd(&h[a * 20 + bb], 1);
            }
        }
    }
    __syncwarp();

    // Integer marginals over the 20x20 block (log2 via L2-resident g_lut)
    int rs = 0, cs = 0;
    if (lane < 20) {
#pragma unroll
        for (int bq = 0; bq < 20; bq++) { rs += h[lane * 20 + bq]; cs += h[bq * 20 + lane]; }
        slra[wid][lane] = __ldg(&g_lut[rs]);
        slcb[wid][lane] = __ldg(&g_lut[cs]);
    }
    int tv = (lane < 20) ? rs : 0;
#pragma unroll
    for (int off = 16; off; off >>= 1) tv += __shfl_xor_sync(0xffffffffu, tv, off);
    int tot = tv;
    __syncwarp();

    int tots = (tot > 0) ? tot : 1;
    float lt = __ldg(&g_lut[tots]);
    float acc = 0.0f;
    for (int c = lane; c < 400; c += 32) {
        int H = h[c];
        if (H > 0) {
            int a = (c * 3277) >> 16;   // c / 20 for c < 400
            int bq = c - a * 20;
            acc += (float)H * (__ldg(&g_lut[H]) - slra[wid][a] - slcb[wid][bq] + lt);
        }
    }
#pragma unroll
    for (int off = 16; off; off >>= 1) acc += __shfl_xor_sync(0xffffffffu, acc, off);

    if (lane == 0) {
        float mi = (tot > 0) ? acc / (float)tots : 0.0f;
        mi_out[i * SEQ_LEN + j] = mi;
        mi_out[j * SEQ_LEN + i] = mi;
    }
}

// ---------------------------------------------------------------------------
// Launch: SINGLE stream, TWO nodes. prep -> mega (zero + pssm hidden in mega).
// ---------------------------------------------------------------------------
extern "C" void kernel_launch(void* const* d_in, const int* in_sizes, int n_in,
                              void* d_out, int out_size) {
    const int*   msa = (const int*)d_in[0];
    const float* pc  = (const float*)d_in[1];
    float*       out = (float*)d_out;

    prep_kernel<<<dim3(16, 16), 256>>>(msa);        // pack + counts + lut
    mega_kernel<<<MEGA_CTAS, 256>>>(out, pc);       // mi + (zero + pssm hidden)
}